// round 6
// baseline (speedup 1.0000x reference)
#include <cuda_runtime.h>

// Problem constants
#define NB 8
#define SEQ 1024
#define DIN 1280
#define RK 64
#define DOUT 1280
#define DOWN_SZ (RK * DIN)      // 81920
#define UP_SZ (DOUT * RK)       // 81920
#define EMB_STRIDE (DOWN_SZ + UP_SZ)
#define KSPLIT 2
#define KHALF (DIN / KSPLIT)    // 640
#define H_ELEMS (NB * SEQ * RK) // 524288

// Scratch for the split-K partial sums of h = x @ W_down^T : 2 x [B,S,RK] fp32 (4 MB)
__device__ float g_h[KSPLIT * H_ELEMS];

// ---------------------------------------------------------------------------
// Down: per batch  C[S, RK] = A[S, DIN] @ W[RK, DIN]^T, split-K = 2.
// blockIdx.x = k-split index; each split writes its own partial buffer.
// Tiles: BM=64, BN=64(=RK), BK=16. 256 threads, 4x4 micro-tile per thread.
// Software-pipelined: next tile's LDGs issued before the compute phase so
// global-load latency overlaps the FFMA block.
// ---------------------------------------------------------------------------
__global__ __launch_bounds__(256) void down_kernel(
    const float* __restrict__ x, const float* __restrict__ embed)
{
    constexpr int BM = 64, BN = 64, BK = 16;
    __shared__ float As[BK][BM + 4];   // stride 68 floats; rows 16B-aligned
    __shared__ float Bs[BK][BN + 4];

    const int tid = threadIdx.x;
    const int ks  = blockIdx.x;         // 0 or 1: K-split
    const int b   = blockIdx.z;
    const int m0  = blockIdx.y * BM;
    const int kbeg = ks * KHALF;
    const int kend = kbeg + KHALF;

    const float* A = x + ((size_t)b * SEQ + m0) * DIN;            // [BM, DIN]
    const float* W = embed + (size_t)b * EMB_STRIDE;              // [RK, DIN]
    float*       C = g_h + (size_t)ks * H_ELEMS
                         + ((size_t)b * SEQ + m0) * RK;           // partial [BM, RK]

    // Global-load mapping: 256 threads cover a 64x16 tile as 64 rows x 4 float4
    const int lrow = tid >> 2;          // 0..63
    const int lcol = (tid & 3) * 4;     // 0,4,8,12

    // Compute mapping: 16x16 thread grid, 4x4 outputs each
    const int trow = (tid >> 4) * 4;    // 0..60
    const int tcol = (tid & 15) * 4;    // 0..60

    float acc[4][4];
#pragma unroll
    for (int i = 0; i < 4; i++)
#pragma unroll
        for (int j = 0; j < 4; j++) acc[i][j] = 0.f;

    // Prologue: load first tile
    float4 av = *(const float4*)(A + (size_t)lrow * DIN + kbeg + lcol);
    float4 bv = *(const float4*)(W + (size_t)lrow * DIN + kbeg + lcol);

    for (int k0 = kbeg; k0 < kend; k0 += BK) {
        __syncthreads();   // previous compute done reading smem
        As[lcol + 0][lrow] = av.x; As[lcol + 1][lrow] = av.y;
        As[lcol + 2][lrow] = av.z; As[lcol + 3][lrow] = av.w;
        Bs[lcol + 0][lrow] = bv.x; Bs[lcol + 1][lrow] = bv.y;
        Bs[lcol + 2][lrow] = bv.z; Bs[lcol + 3][lrow] = bv.w;
        __syncthreads();

        // Prefetch next tile while computing this one
        if (k0 + BK < kend) {
            av = *(const float4*)(A + (size_t)lrow * DIN + k0 + BK + lcol);
            bv = *(const float4*)(W + (size_t)lrow * DIN + k0 + BK + lcol);
        }

#pragma unroll
        for (int k = 0; k < BK; k++) {
            float4 a = *(const float4*)&As[k][trow];
            float4 bb = *(const float4*)&Bs[k][tcol];
            acc[0][0] += a.x * bb.x; acc[0][1] += a.x * bb.y;
            acc[0][2] += a.x * bb.z; acc[0][3] += a.x * bb.w;
            acc[1][0] += a.y * bb.x; acc[1][1] += a.y * bb.y;
            acc[1][2] += a.y * bb.z; acc[1][3] += a.y * bb.w;
            acc[2][0] += a.z * bb.x; acc[2][1] += a.z * bb.y;
            acc[2][2] += a.z * bb.z; acc[2][3] += a.z * bb.w;
            acc[3][0] += a.w * bb.x; acc[3][1] += a.w * bb.y;
            acc[3][2] += a.w * bb.z; acc[3][3] += a.w * bb.w;
        }
    }

#pragma unroll
    for (int i = 0; i < 4; i++) {
        float4 v = make_float4(acc[i][0], acc[i][1], acc[i][2], acc[i][3]);
        *(float4*)(C + (size_t)(trow + i) * RK + tcol) = v;
    }
}

// ---------------------------------------------------------------------------
// Up: per batch  C[S, DOUT] = h[S, RK] @ Wup[DOUT, RK]^T
// h is summed from the two split-K partial buffers during the A-tile fill.
// Same tiling; K = RK = 64 (4 BK-iterations), software-pipelined.
// ---------------------------------------------------------------------------
__global__ __launch_bounds__(256) void up_kernel(
    const float* __restrict__ embed, float* __restrict__ out)
{
    constexpr int BM = 64, BN = 64, BK = 16;
    __shared__ float As[BK][BM + 4];
    __shared__ float Bs[BK][BN + 4];

    const int tid = threadIdx.x;
    const int b   = blockIdx.z;
    const int m0  = blockIdx.y * BM;
    const int n0  = blockIdx.x * BN;

    const float* A0 = g_h + ((size_t)b * SEQ + m0) * RK;                         // partial 0
    const float* A1 = A0 + (size_t)H_ELEMS;                                      // partial 1
    const float* W  = embed + (size_t)b * EMB_STRIDE + DOWN_SZ + (size_t)n0 * RK; // [BN, RK]
    float*       C  = out + ((size_t)b * SEQ + m0) * DOUT + n0;

    const int lrow = tid >> 2;
    const int lcol = (tid & 3) * 4;
    const int trow = (tid >> 4) * 4;
    const int tcol = (tid & 15) * 4;

    float acc[4][4];
#pragma unroll
    for (int i = 0; i < 4; i++)
#pragma unroll
        for (int j = 0; j < 4; j++) acc[i][j] = 0.f;

    // Prologue: load first tile (sum the two split-K partials on the fly)
    float4 av, bv;
    {
        const size_t aoff = (size_t)lrow * RK + lcol;
        av = *(const float4*)(A0 + aoff);
        float4 av1 = *(const float4*)(A1 + aoff);
        av.x += av1.x; av.y += av1.y; av.z += av1.z; av.w += av1.w;
        bv = *(const float4*)(W + (size_t)lrow * RK + lcol);
    }

#pragma unroll
    for (int k0 = 0; k0 < RK; k0 += BK) {
        __syncthreads();
        As[lcol + 0][lrow] = av.x; As[lcol + 1][lrow] = av.y;
        As[lcol + 2][lrow] = av.z; As[lcol + 3][lrow] = av.w;
        Bs[lcol + 0][lrow] = bv.x; Bs[lcol + 1][lrow] = bv.y;
        Bs[lcol + 2][lrow] = bv.z; Bs[lcol + 3][lrow] = bv.w;
        __syncthreads();

        if (k0 + BK < RK) {
            const size_t aoff = (size_t)lrow * RK + k0 + BK + lcol;
            av = *(const float4*)(A0 + aoff);
            float4 av1 = *(const float4*)(A1 + aoff);
            av.x += av1.x; av.y += av1.y; av.z += av1.z; av.w += av1.w;
            bv = *(const float4*)(W + (size_t)lrow * RK + k0 + BK + lcol);
        }

#pragma unroll
        for (int k = 0; k < BK; k++) {
            float4 a = *(const float4*)&As[k][trow];
            float4 bb = *(const float4*)&Bs[k][tcol];
            acc[0][0] += a.x * bb.x; acc[0][1] += a.x * bb.y;
            acc[0][2] += a.x * bb.z; acc[0][3] += a.x * bb.w;
            acc[1][0] += a.y * bb.x; acc[1][1] += a.y * bb.y;
            acc[1][2] += a.y * bb.z; acc[1][3] += a.y * bb.w;
            acc[2][0] += a.z * bb.x; acc[2][1] += a.z * bb.y;
            acc[2][2] += a.z * bb.z; acc[2][3] += a.z * bb.w;
            acc[3][0] += a.w * bb.x; acc[3][1] += a.w * bb.y;
            acc[3][2] += a.w * bb.z; acc[3][3] += a.w * bb.w;
        }
    }

#pragma unroll
    for (int i = 0; i < 4; i++) {
        float4 v = make_float4(acc[i][0], acc[i][1], acc[i][2], acc[i][3]);
        *(float4*)(C + (size_t)(trow + i) * DOUT + tcol) = v;
    }
}

extern "C" void kernel_launch(void* const* d_in, const int* in_sizes, int n_in,
                              void* d_out, int out_size)
{
    const float* x     = (const float*)d_in[0];   // [B, S, D_IN] fp32
    const float* embed = (const float*)d_in[1];   // [B, DOWN+UP] fp32
    float*       out   = (float*)d_out;           // [B, S, D_OUT] fp32

    (void)in_sizes; (void)n_in; (void)out_size;

    // down: h partials = x @ W_down^T  (grid: 2 x 16 x 8 = 256 blocks, SM-balanced)
    down_kernel<<<dim3(KSPLIT, SEQ / 64, NB), 256>>>(x, embed);
    // up: out = (h0 + h1) @ W_up^T     (grid: 20 x 16 x 8 = 2560 blocks)
    up_kernel<<<dim3(DOUT / 64, SEQ / 64, NB), 256>>>(embed, out);
}

// round 8
// speedup vs baseline: 1.0804x; 1.0804x over previous
#include <cuda_runtime.h>

// Problem constants
#define NB 8
#define SEQ 1024
#define DIN 1280
#define RK 64
#define DOUT 1280
#define DOWN_SZ (RK * DIN)      // 81920
#define UP_SZ (DOUT * RK)       // 81920
#define EMB_STRIDE (DOWN_SZ + UP_SZ)
#define KSPLIT 4
#define KCHUNK (DIN / KSPLIT)   // 320
#define H_ELEMS (NB * SEQ * RK) // 524288

// Split-K partial sums of h = x @ W_down^T : KSPLIT x [B,S,RK] fp32 (8 MB)
__device__ float g_h[KSPLIT * H_ELEMS];
// Reduced h (2 MB)
__device__ float g_hr[H_ELEMS];

// ---------------------------------------------------------------------------
// Down: per batch  C[S, RK] = A[S, DIN] @ W[RK, DIN]^T, split-K = 4.
// BM=128, BN=64(=RK), BK=16. 256 threads, 8x4 micro-tile.
// 32 FFMA per 3 LDS.128 in the inner loop; global loads software-pipelined.
// ---------------------------------------------------------------------------
__global__ __launch_bounds__(256) void down_kernel(
    const float* __restrict__ x, const float* __restrict__ embed)
{
    constexpr int BM = 128, BK = 16;
    __shared__ float As[BK][BM + 4];   // transposed, stride 132 floats
    __shared__ float Bs[BK][RK + 4];

    const int tid  = threadIdx.x;
    const int ks   = blockIdx.x;        // 0..3: K-split
    const int b    = blockIdx.z;
    const int m0   = blockIdx.y * BM;
    const int kbeg = ks * KCHUNK;
    const int kend = kbeg + KCHUNK;

    const float* A = x + ((size_t)b * SEQ + m0) * DIN;            // [BM, DIN]
    const float* W = embed + (size_t)b * EMB_STRIDE;              // [RK, DIN]
    float*       C = g_h + (size_t)ks * H_ELEMS
                         + ((size_t)b * SEQ + m0) * RK;           // partial [BM, RK]

    // Global-load mapping: 256 threads, 64 rows x 4 float4 per pass
    const int lrow = tid >> 2;          // 0..63
    const int lcol = (tid & 3) * 4;     // 0,4,8,12

    // Compute mapping: 16x16 thread grid, 8x4 outputs each
    const int trow = (tid >> 4) * 8;    // 0..120
    const int tcol = (tid & 15) * 4;    // 0..60

    float acc[8][4];
#pragma unroll
    for (int i = 0; i < 8; i++)
#pragma unroll
        for (int j = 0; j < 4; j++) acc[i][j] = 0.f;

    // Prologue: load first tile (A: two 64-row halves; B: 64 rows)
    float4 av0 = *(const float4*)(A + (size_t)lrow        * DIN + kbeg + lcol);
    float4 av1 = *(const float4*)(A + (size_t)(lrow + 64) * DIN + kbeg + lcol);
    float4 bv  = *(const float4*)(W + (size_t)lrow        * DIN + kbeg + lcol);

    for (int k0 = kbeg; k0 < kend; k0 += BK) {
        __syncthreads();
        As[lcol + 0][lrow] = av0.x; As[lcol + 1][lrow] = av0.y;
        As[lcol + 2][lrow] = av0.z; As[lcol + 3][lrow] = av0.w;
        As[lcol + 0][lrow + 64] = av1.x; As[lcol + 1][lrow + 64] = av1.y;
        As[lcol + 2][lrow + 64] = av1.z; As[lcol + 3][lrow + 64] = av1.w;
        Bs[lcol + 0][lrow] = bv.x; Bs[lcol + 1][lrow] = bv.y;
        Bs[lcol + 2][lrow] = bv.z; Bs[lcol + 3][lrow] = bv.w;
        __syncthreads();

        if (k0 + BK < kend) {   // prefetch next tile over the FFMA block
            av0 = *(const float4*)(A + (size_t)lrow        * DIN + k0 + BK + lcol);
            av1 = *(const float4*)(A + (size_t)(lrow + 64) * DIN + k0 + BK + lcol);
            bv  = *(const float4*)(W + (size_t)lrow        * DIN + k0 + BK + lcol);
        }

#pragma unroll
        for (int k = 0; k < BK; k++) {
            float4 a0 = *(const float4*)&As[k][trow];
            float4 a1 = *(const float4*)&As[k][trow + 4];
            float4 bb = *(const float4*)&Bs[k][tcol];
            acc[0][0] += a0.x * bb.x; acc[0][1] += a0.x * bb.y; acc[0][2] += a0.x * bb.z; acc[0][3] += a0.x * bb.w;
            acc[1][0] += a0.y * bb.x; acc[1][1] += a0.y * bb.y; acc[1][2] += a0.y * bb.z; acc[1][3] += a0.y * bb.w;
            acc[2][0] += a0.z * bb.x; acc[2][1] += a0.z * bb.y; acc[2][2] += a0.z * bb.z; acc[2][3] += a0.z * bb.w;
            acc[3][0] += a0.w * bb.x; acc[3][1] += a0.w * bb.y; acc[3][2] += a0.w * bb.z; acc[3][3] += a0.w * bb.w;
            acc[4][0] += a1.x * bb.x; acc[4][1] += a1.x * bb.y; acc[4][2] += a1.x * bb.z; acc[4][3] += a1.x * bb.w;
            acc[5][0] += a1.y * bb.x; acc[5][1] += a1.y * bb.y; acc[5][2] += a1.y * bb.z; acc[5][3] += a1.y * bb.w;
            acc[6][0] += a1.z * bb.x; acc[6][1] += a1.z * bb.y; acc[6][2] += a1.z * bb.z; acc[6][3] += a1.z * bb.w;
            acc[7][0] += a1.w * bb.x; acc[7][1] += a1.w * bb.y; acc[7][2] += a1.w * bb.z; acc[7][3] += a1.w * bb.w;
        }
    }

#pragma unroll
    for (int i = 0; i < 8; i++) {
        float4 v = make_float4(acc[i][0], acc[i][1], acc[i][2], acc[i][3]);
        *(float4*)(C + (size_t)(trow + i) * RK + tcol) = v;
    }
}

// ---------------------------------------------------------------------------
// Reduce the KSPLIT partial h buffers into g_hr. float4 per thread.
// ---------------------------------------------------------------------------
__global__ __launch_bounds__(256) void reduce_kernel()
{
    const int i = (blockIdx.x * 256 + threadIdx.x) * 4;
    float4 s = *(const float4*)&g_h[i];
#pragma unroll
    for (int p = 1; p < KSPLIT; p++) {
        float4 v = *(const float4*)&g_h[(size_t)p * H_ELEMS + i];
        s.x += v.x; s.y += v.y; s.z += v.z; s.w += v.w;
    }
    *(float4*)&g_hr[i] = s;
}

// ---------------------------------------------------------------------------
// Up: per batch  C[S, DOUT] = h[S, RK] @ Wup[DOUT, RK]^T
// BM=128, BN=128, BK=16. 256 threads, 8x8 micro-tile: 64 FFMA per 4 LDS.128.
// K = RK = 64 (4 BK-iterations), software-pipelined.
// ---------------------------------------------------------------------------
__global__ __launch_bounds__(256) void up_kernel(
    const float* __restrict__ embed, float* __restrict__ out)
{
    constexpr int BM = 128, BN = 128, BK = 16;
    __shared__ float As[BK][BM + 4];
    __shared__ float Bs[BK][BN + 4];

    const int tid = threadIdx.x;
    const int b   = blockIdx.z;
    const int m0  = blockIdx.y * BM;
    const int n0  = blockIdx.x * BN;

    const float* A = g_hr + ((size_t)b * SEQ + m0) * RK;                          // [BM, RK]
    const float* W = embed + (size_t)b * EMB_STRIDE + DOWN_SZ + (size_t)n0 * RK;  // [BN, RK]
    float*       C = out + ((size_t)b * SEQ + m0) * DOUT + n0;

    const int lrow = tid >> 2;          // 0..63
    const int lcol = (tid & 3) * 4;     // 0,4,8,12
    const int trow = (tid >> 4) * 8;    // 0..120
    const int tcol = (tid & 15) * 8;    // 0..120

    float acc[8][8];
#pragma unroll
    for (int i = 0; i < 8; i++)
#pragma unroll
        for (int j = 0; j < 8; j++) acc[i][j] = 0.f;

    // Prologue: first tile
    float4 av0 = *(const float4*)(A + (size_t)lrow        * RK + lcol);
    float4 av1 = *(const float4*)(A + (size_t)(lrow + 64) * RK + lcol);
    float4 bv0 = *(const float4*)(W + (size_t)lrow        * RK + lcol);
    float4 bv1 = *(const float4*)(W + (size_t)(lrow + 64) * RK + lcol);

#pragma unroll
    for (int k0 = 0; k0 < RK; k0 += BK) {
        __syncthreads();
        As[lcol + 0][lrow] = av0.x; As[lcol + 1][lrow] = av0.y;
        As[lcol + 2][lrow] = av0.z; As[lcol + 3][lrow] = av0.w;
        As[lcol + 0][lrow + 64] = av1.x; As[lcol + 1][lrow + 64] = av1.y;
        As[lcol + 2][lrow + 64] = av1.z; As[lcol + 3][lrow + 64] = av1.w;
        Bs[lcol + 0][lrow] = bv0.x; Bs[lcol + 1][lrow] = bv0.y;
        Bs[lcol + 2][lrow] = bv0.z; Bs[lcol + 3][lrow] = bv0.w;
        Bs[lcol + 0][lrow + 64] = bv1.x; Bs[lcol + 1][lrow + 64] = bv1.y;
        Bs[lcol + 2][lrow + 64] = bv1.z; Bs[lcol + 3][lrow + 64] = bv1.w;
        __syncthreads();

        if (k0 + BK < RK) {   // prefetch next tile over the FFMA block
            av0 = *(const float4*)(A + (size_t)lrow        * RK + k0 + BK + lcol);
            av1 = *(const float4*)(A + (size_t)(lrow + 64) * RK + k0 + BK + lcol);
            bv0 = *(const float4*)(W + (size_t)lrow        * RK + k0 + BK + lcol);
            bv1 = *(const float4*)(W + (size_t)(lrow + 64) * RK + k0 + BK + lcol);
        }

#pragma unroll
        for (int k = 0; k < BK; k++) {
            float4 a0 = *(const float4*)&As[k][trow];
            float4 a1 = *(const float4*)&As[k][trow + 4];
            float4 b0 = *(const float4*)&Bs[k][tcol];
            float4 b1 = *(const float4*)&Bs[k][tcol + 4];
            const float ar[8] = {a0.x, a0.y, a0.z, a0.w, a1.x, a1.y, a1.z, a1.w};
            const float br[8] = {b0.x, b0.y, b0.z, b0.w, b1.x, b1.y, b1.z, b1.w};
#pragma unroll
            for (int i = 0; i < 8; i++)
#pragma unroll
                for (int j = 0; j < 8; j++)
                    acc[i][j] += ar[i] * br[j];
        }
    }

#pragma unroll
    for (int i = 0; i < 8; i++) {
        float4 v0 = make_float4(acc[i][0], acc[i][1], acc[i][2], acc[i][3]);
        float4 v1 = make_float4(acc[i][4], acc[i][5], acc[i][6], acc[i][7]);
        *(float4*)(C + (size_t)(trow + i) * DOUT + tcol)     = v0;
        *(float4*)(C + (size_t)(trow + i) * DOUT + tcol + 4) = v1;
    }
}

extern "C" void kernel_launch(void* const* d_in, const int* in_sizes, int n_in,
                              void* d_out, int out_size)
{
    const float* x     = (const float*)d_in[0];   // [B, S, D_IN] fp32
    const float* embed = (const float*)d_in[1];   // [B, DOWN+UP] fp32
    float*       out   = (float*)d_out;           // [B, S, D_OUT] fp32

    (void)in_sizes; (void)n_in; (void)out_size;

    // down: h partials = x @ W_down^T  (grid: 4 x 8 x 8 = 256 blocks)
    down_kernel<<<dim3(KSPLIT, SEQ / 128, NB), 256>>>(x, embed);
    // reduce the 4 partials into g_hr (524288 elems / 4 per thread / 256)
    reduce_kernel<<<H_ELEMS / 4 / 256, 256>>>();
    // up: out = h @ W_up^T  (grid: 10 x 8 x 8 = 640 blocks)
    up_kernel<<<dim3(DOUT / 128, SEQ / 128, NB), 256>>>(embed, out);
}

// round 11
// speedup vs baseline: 1.5313x; 1.4173x over previous
#include <cuda_runtime.h>
#include <cuda_bf16.h>
#include <cstdint>

// ---------------------------------------------------------------- constants
#define NB 8
#define SEQ 1024
#define DIN 1280
#define RK 64
#define DOUT 1280
#define DOWN_SZ (RK * DIN)        // 81920
#define UP_SZ (DOUT * RK)         // 81920
#define EMB_STRIDE (DOWN_SZ + UP_SZ)
#define H_ELEMS (NB * SEQ * RK)   // 524288

// ------------------------------------------------------------ device scratch
__device__ float         g_h[H_ELEMS];              // h fp32 (2 MB)
__device__ __nv_bfloat16 g_w_hi[NB * EMB_STRIDE];   // embed split hi/lo bf16
__device__ __nv_bfloat16 g_w_lo[NB * EMB_STRIDE];

// ---------------------------------------------------------------- helpers
__device__ __forceinline__ uint32_t s2u(const void* p) {
    uint32_t a;
    asm("{ .reg .u64 t; cvta.to.shared.u64 t, %1; cvt.u32.u64 %0, t; }" : "=r"(a) : "l"(p));
    return a;
}
__device__ __forceinline__ void split2(float x, uint16_t& h, uint16_t& l) {
    __nv_bfloat16 hb = __float2bfloat16(x);
    __nv_bfloat16 lb = __float2bfloat16(x - __bfloat162float(hb));
    h = *(uint16_t*)&hb; l = *(uint16_t*)&lb;
}
__device__ __forceinline__ uint32_t pk(uint16_t a, uint16_t b) {
    return (uint32_t)a | ((uint32_t)b << 16);
}
__device__ __forceinline__ void split8(float4 v0, float4 v1, uint4& hh, uint4& ll) {
    uint16_t h[8], l[8];
    split2(v0.x, h[0], l[0]); split2(v0.y, h[1], l[1]);
    split2(v0.z, h[2], l[2]); split2(v0.w, h[3], l[3]);
    split2(v1.x, h[4], l[4]); split2(v1.y, h[5], l[5]);
    split2(v1.z, h[6], l[6]); split2(v1.w, h[7], l[7]);
    hh = make_uint4(pk(h[0],h[1]), pk(h[2],h[3]), pk(h[4],h[5]), pk(h[6],h[7]));
    ll = make_uint4(pk(l[0],l[1]), pk(l[2],l[3]), pk(l[4],l[5]), pk(l[6],l[7]));
}
// ldmatrix x4, non-transposed
__device__ __forceinline__ void ldsm4(uint32_t r[4], uint32_t addr) {
    asm volatile("ldmatrix.sync.aligned.m8n8.x4.shared.b16 {%0,%1,%2,%3}, [%4];"
        : "=r"(r[0]), "=r"(r[1]), "=r"(r[2]), "=r"(r[3]) : "r"(addr));
}
// D += A(16x16) * B(16x8), bf16 in, fp32 acc
__device__ __forceinline__ void mma_bf16(float d[4], const uint32_t a[4],
                                         uint32_t b0, uint32_t b1) {
    asm volatile(
        "mma.sync.aligned.m16n8k16.row.col.f32.bf16.bf16.f32 "
        "{%0,%1,%2,%3}, {%4,%5,%6,%7}, {%8,%9}, {%0,%1,%2,%3};"
        : "+f"(d[0]), "+f"(d[1]), "+f"(d[2]), "+f"(d[3])
        : "r"(a[0]), "r"(a[1]), "r"(a[2]), "r"(a[3]), "r"(b0), "r"(b1));
}

// ---------------------------------------------------------------------------
// prep: split embed (fp32) into bf16 hi/lo, same flat layout.
// ---------------------------------------------------------------------------
__global__ __launch_bounds__(256) void prep_kernel(const float* __restrict__ embed)
{
    size_t i = ((size_t)blockIdx.x * 256 + threadIdx.x) * 4;
    float4 v = *(const float4*)(embed + i);
    uint16_t h0, l0, h1, l1, h2, l2, h3, l3;
    split2(v.x, h0, l0); split2(v.y, h1, l1);
    split2(v.z, h2, l2); split2(v.w, h3, l3);
    *(uint2*)(g_w_hi + i) = make_uint2(pk(h0, h1), pk(h2, h3));
    *(uint2*)(g_w_lo + i) = make_uint2(pk(l0, l1), pk(l2, l3));
}

// ---------------------------------------------------------------------------
// down: h = x @ Wdown^T  (per batch M=1024, N=64, K=1280), bf16x3 mma.sync.
// CTA: 64 rows x 64 cols, K-chunks of 64. 8 warps, warp tile 32x16.
// Smem rows have 72-element stride -> conflict-free STS + ldmatrix.
// ---------------------------------------------------------------------------
#define DST 72              // smem row stride in bf16 elems
__global__ __launch_bounds__(256) void down_kernel(const float* __restrict__ x)
{
    __shared__ __align__(16) uint16_t sm[4 * 64 * DST];
    uint16_t* AH = sm;
    uint16_t* AL = sm + 64 * DST;
    uint16_t* BH = sm + 2 * 64 * DST;
    uint16_t* BL = sm + 3 * 64 * DST;

    const int tid = threadIdx.x, lane = tid & 31, wid = tid >> 5;
    const int mt = blockIdx.x, b = blockIdx.y;

    const float* A = x + ((size_t)b * SEQ + (size_t)mt * 64) * DIN;
    const __nv_bfloat16* WH = g_w_hi + (size_t)b * EMB_STRIDE;
    const __nv_bfloat16* WL = g_w_lo + (size_t)b * EMB_STRIDE;
    float* C = g_h + ((size_t)b * SEQ + (size_t)mt * 64) * RK;

    // loader mapping: thread -> (row 0..63, 16-col segment)
    const int lrow = tid >> 2, lcs = (tid & 3) * 16;
    // warp tiling: 2 (M) x 4 (N)
    const int wm = (wid & 1) * 32, wn = (wid >> 1) * 16;

    const uint32_t ahb = s2u(AH), alb = s2u(AL), bhb = s2u(BH), blb = s2u(BL);
    // ldmatrix lane offsets (elements)
    const int aoff = (lane & 15) * DST + (lane >> 4) * 8;
    const int boff = (((lane >> 3) & 1) * 8 + (lane & 7)) * DST + (lane >> 4) * 8;

    float acc[2][2][4];
#pragma unroll
    for (int i = 0; i < 2; i++)
#pragma unroll
        for (int j = 0; j < 2; j++)
#pragma unroll
            for (int q = 0; q < 4; q++) acc[i][j][q] = 0.f;

    // prefetch chunk 0
    float4 xv0, xv1, xv2, xv3;
    uint4 whv0, whv1, wlv0, wlv1;
    {
        const float* ap = A + (size_t)lrow * DIN + lcs;
        xv0 = *(const float4*)ap;       xv1 = *(const float4*)(ap + 4);
        xv2 = *(const float4*)(ap + 8); xv3 = *(const float4*)(ap + 12);
        const __nv_bfloat16* wp = WH + (size_t)lrow * DIN + lcs;
        whv0 = *(const uint4*)wp; whv1 = *(const uint4*)(wp + 8);
        wp = WL + (size_t)lrow * DIN + lcs;
        wlv0 = *(const uint4*)wp; wlv1 = *(const uint4*)(wp + 8);
    }

    for (int ch = 0; ch < DIN / 64; ch++) {
        if (ch) __syncthreads();             // previous compute done with smem
        uint4 hh0, ll0, hh1, ll1;
        split8(xv0, xv1, hh0, ll0);
        split8(xv2, xv3, hh1, ll1);
        {
            uint16_t* p = AH + lrow * DST + lcs;
            *(uint4*)p = hh0; *(uint4*)(p + 8) = hh1;
            p = AL + lrow * DST + lcs;
            *(uint4*)p = ll0; *(uint4*)(p + 8) = ll1;
            p = BH + lrow * DST + lcs;
            *(uint4*)p = whv0; *(uint4*)(p + 8) = whv1;
            p = BL + lrow * DST + lcs;
            *(uint4*)p = wlv0; *(uint4*)(p + 8) = wlv1;
        }
        __syncthreads();

        if (ch + 1 < DIN / 64) {             // prefetch next chunk over MMAs
            const int kc = (ch + 1) * 64;
            const float* ap = A + (size_t)lrow * DIN + kc + lcs;
            xv0 = *(const float4*)ap;       xv1 = *(const float4*)(ap + 4);
            xv2 = *(const float4*)(ap + 8); xv3 = *(const float4*)(ap + 12);
            const __nv_bfloat16* wp = WH + (size_t)lrow * DIN + kc + lcs;
            whv0 = *(const uint4*)wp; whv1 = *(const uint4*)(wp + 8);
            wp = WL + (size_t)lrow * DIN + kc + lcs;
            wlv0 = *(const uint4*)wp; wlv1 = *(const uint4*)(wp + 8);
        }

#pragma unroll
        for (int ks = 0; ks < 4; ks++) {
            const int kb = ks * 16;
            uint32_t ah0[4], ah1[4], al0[4], al1[4], bh[4], bl[4];
            ldsm4(ah0, ahb + (uint32_t)(wm * DST + kb + aoff) * 2);
            ldsm4(ah1, ahb + (uint32_t)((wm + 16) * DST + kb + aoff) * 2);
            ldsm4(al0, alb + (uint32_t)(wm * DST + kb + aoff) * 2);
            ldsm4(al1, alb + (uint32_t)((wm + 16) * DST + kb + aoff) * 2);
            ldsm4(bh,  bhb + (uint32_t)(wn * DST + kb + boff) * 2);
            ldsm4(bl,  blb + (uint32_t)(wn * DST + kb + boff) * 2);
            // bh regs: {b0 nf0, b0 nf1, b1 nf0, b1 nf1}
            mma_bf16(acc[0][0], ah0, bh[0], bh[2]);
            mma_bf16(acc[0][0], ah0, bl[0], bl[2]);
            mma_bf16(acc[0][0], al0, bh[0], bh[2]);
            mma_bf16(acc[0][1], ah0, bh[1], bh[3]);
            mma_bf16(acc[0][1], ah0, bl[1], bl[3]);
            mma_bf16(acc[0][1], al0, bh[1], bh[3]);
            mma_bf16(acc[1][0], ah1, bh[0], bh[2]);
            mma_bf16(acc[1][0], ah1, bl[0], bl[2]);
            mma_bf16(acc[1][0], al1, bh[0], bh[2]);
            mma_bf16(acc[1][1], ah1, bh[1], bh[3]);
            mma_bf16(acc[1][1], ah1, bl[1], bl[3]);
            mma_bf16(acc[1][1], al1, bh[1], bh[3]);
        }
    }

    // epilogue: write h fp32
    const int er = lane >> 2, ec = (lane & 3) * 2;
#pragma unroll
    for (int mf = 0; mf < 2; mf++)
#pragma unroll
        for (int nf = 0; nf < 2; nf++) {
            float* c0 = C + (size_t)(wm + mf * 16 + er) * RK + wn + nf * 8 + ec;
            *(float2*)c0            = make_float2(acc[mf][nf][0], acc[mf][nf][1]);
            *(float2*)(c0 + 8 * RK) = make_float2(acc[mf][nf][2], acc[mf][nf][3]);
        }
}

// ---------------------------------------------------------------------------
// up: out = h @ Wup^T (per batch M=1024, N=1280, K=64), bf16x3 mma.sync.
// CTA: 128x128, single K-chunk. 8 warps, warp tile 32x64.
// ---------------------------------------------------------------------------
#define UP_SMEM_ELEMS (4 * 128 * DST)
__global__ __launch_bounds__(256) void up_kernel(float* __restrict__ out)
{
    extern __shared__ __align__(16) uint16_t usm[];
    uint16_t* AH = usm;
    uint16_t* AL = usm + 128 * DST;
    uint16_t* BH = usm + 2 * 128 * DST;
    uint16_t* BL = usm + 3 * 128 * DST;

    const int tid = threadIdx.x, lane = tid & 31, wid = tid >> 5;
    const int nt = blockIdx.x, mt = blockIdx.y, b = blockIdx.z;

    const float* Hsrc = g_h + ((size_t)b * SEQ + (size_t)mt * 128) * RK;
    const __nv_bfloat16* WH = g_w_hi + (size_t)b * EMB_STRIDE + DOWN_SZ + (size_t)nt * 128 * RK;
    const __nv_bfloat16* WL = g_w_lo + (size_t)b * EMB_STRIDE + DOWN_SZ + (size_t)nt * 128 * RK;
    float* O = out + ((size_t)b * SEQ + (size_t)mt * 128) * DOUT + (size_t)nt * 128;

    // loaders: thread -> (row 0..127, 32-col segment)
    const int lrow = tid >> 1, lcs = (tid & 1) * 32;
    {
        const float* hp = Hsrc + (size_t)lrow * RK + lcs;
#pragma unroll
        for (int j = 0; j < 4; j++) {
            float4 v0 = *(const float4*)(hp + j * 8);
            float4 v1 = *(const float4*)(hp + j * 8 + 4);
            uint4 hh, ll;
            split8(v0, v1, hh, ll);
            *(uint4*)(AH + lrow * DST + lcs + j * 8) = hh;
            *(uint4*)(AL + lrow * DST + lcs + j * 8) = ll;
        }
        const __nv_bfloat16* wh = WH + (size_t)lrow * RK + lcs;
        const __nv_bfloat16* wl = WL + (size_t)lrow * RK + lcs;
#pragma unroll
        for (int j = 0; j < 4; j++) {
            *(uint4*)(BH + lrow * DST + lcs + j * 8) = *(const uint4*)(wh + j * 8);
            *(uint4*)(BL + lrow * DST + lcs + j * 8) = *(const uint4*)(wl + j * 8);
        }
    }
    __syncthreads();

    // warp tiling: 4 (M) x 2 (N); warp tile 32 x 64
    const int wm = (wid & 3) * 32, wn = (wid >> 2) * 64;
    const uint32_t ahb = s2u(AH), alb = s2u(AL), bhb = s2u(BH), blb = s2u(BL);
    const int aoff = (lane & 15) * DST + (lane >> 4) * 8;
    const int boff = (((lane >> 3) & 1) * 8 + (lane & 7)) * DST + (lane >> 4) * 8;

    float acc[2][8][4];
#pragma unroll
    for (int i = 0; i < 2; i++)
#pragma unroll
        for (int j = 0; j < 8; j++)
#pragma unroll
            for (int q = 0; q < 4; q++) acc[i][j][q] = 0.f;

#pragma unroll
    for (int ks = 0; ks < 4; ks++) {
        const int kb = ks * 16;
        uint32_t ah[2][4], al[2][4];
        ldsm4(ah[0], ahb + (uint32_t)(wm * DST + kb + aoff) * 2);
        ldsm4(ah[1], ahb + (uint32_t)((wm + 16) * DST + kb + aoff) * 2);
        ldsm4(al[0], alb + (uint32_t)(wm * DST + kb + aoff) * 2);
        ldsm4(al[1], alb + (uint32_t)((wm + 16) * DST + kb + aoff) * 2);
        uint32_t bh[4][4], bl[4][4];   // pair p covers nfrags 2p, 2p+1
#pragma unroll
        for (int p = 0; p < 4; p++) {
            ldsm4(bh[p], bhb + (uint32_t)((wn + p * 16) * DST + kb + boff) * 2);
            ldsm4(bl[p], blb + (uint32_t)((wn + p * 16) * DST + kb + boff) * 2);
        }
#pragma unroll
        for (int mf = 0; mf < 2; mf++)
#pragma unroll
            for (int p = 0; p < 4; p++) {
                mma_bf16(acc[mf][2*p],   ah[mf], bh[p][0], bh[p][2]);
                mma_bf16(acc[mf][2*p],   ah[mf], bl[p][0], bl[p][2]);
                mma_bf16(acc[mf][2*p],   al[mf], bh[p][0], bh[p][2]);
                mma_bf16(acc[mf][2*p+1], ah[mf], bh[p][1], bh[p][3]);
                mma_bf16(acc[mf][2*p+1], ah[mf], bl[p][1], bl[p][3]);
                mma_bf16(acc[mf][2*p+1], al[mf], bh[p][1], bh[p][3]);
            }
    }

    // epilogue: direct fp32 stores
    const int er = lane >> 2, ec = (lane & 3) * 2;
#pragma unroll
    for (int mf = 0; mf < 2; mf++)
#pragma unroll
        for (int nf = 0; nf < 8; nf++) {
            float* c0 = O + (size_t)(wm + mf * 16 + er) * DOUT + wn + nf * 8 + ec;
            *(float2*)c0              = make_float2(acc[mf][nf][0], acc[mf][nf][1]);
            *(float2*)(c0 + 8 * DOUT) = make_float2(acc[mf][nf][2], acc[mf][nf][3]);
        }
}

// ---------------------------------------------------------------------------
extern "C" void kernel_launch(void* const* d_in, const int* in_sizes, int n_in,
                              void* d_out, int out_size)
{
    const float* x     = (const float*)d_in[0];   // [B, S, D_IN] fp32
    const float* embed = (const float*)d_in[1];   // [B, DOWN+UP] fp32
    float*       out   = (float*)d_out;           // [B, S, D_OUT] fp32
    (void)in_sizes; (void)n_in; (void)out_size;

    cudaFuncSetAttribute(up_kernel, cudaFuncAttributeMaxDynamicSharedMemorySize,
                         UP_SMEM_ELEMS * 2);

    // 1) split embed into bf16 hi/lo
    prep_kernel<<<NB * EMB_STRIDE / 1024, 256>>>(embed);
    // 2) down GEMM: grid 16 x 8 = 128 CTAs
    down_kernel<<<dim3(SEQ / 64, NB), 256>>>(x);
    // 3) up GEMM: grid 10 x 8 x 8 = 640 CTAs
    up_kernel<<<dim3(DOUT / 128, SEQ / 128, NB), 256, UP_SMEM_ELEMS * 2>>>(out);
}

// round 12
// speedup vs baseline: 1.6402x; 1.0711x over previous
#include <cuda_runtime.h>
#include <cuda_bf16.h>
#include <cstdint>

// ---------------------------------------------------------------- constants
#define NB 8
#define SEQ 1024
#define DIN 1280
#define RK 64
#define DOUT 1280
#define DOWN_SZ (RK * DIN)        // 81920
#define UP_SZ (DOUT * RK)         // 81920
#define EMB_STRIDE (DOWN_SZ + UP_SZ)
#define H_ELEMS (NB * SEQ * RK)   // 524288
#define KSPLIT 2
#define KHALF (DIN / KSPLIT)      // 640

// ------------------------------------------------------------ device scratch
__device__ float         g_hpart[KSPLIT * H_ELEMS]; // split-K fp32 partials (4 MB)
__device__ __nv_bfloat16 g_h_hi[H_ELEMS];           // reduced h, bf16 hi/lo (2 MB)
__device__ __nv_bfloat16 g_h_lo[H_ELEMS];
__device__ __nv_bfloat16 g_w_hi[NB * EMB_STRIDE];   // embed split hi/lo bf16
__device__ __nv_bfloat16 g_w_lo[NB * EMB_STRIDE];

// ---------------------------------------------------------------- helpers
__device__ __forceinline__ uint32_t s2u(const void* p) {
    uint32_t a;
    asm("{ .reg .u64 t; cvta.to.shared.u64 t, %1; cvt.u32.u64 %0, t; }" : "=r"(a) : "l"(p));
    return a;
}
__device__ __forceinline__ void split2(float x, uint16_t& h, uint16_t& l) {
    __nv_bfloat16 hb = __float2bfloat16(x);
    __nv_bfloat16 lb = __float2bfloat16(x - __bfloat162float(hb));
    h = *(uint16_t*)&hb; l = *(uint16_t*)&lb;
}
__device__ __forceinline__ uint32_t pk(uint16_t a, uint16_t b) {
    return (uint32_t)a | ((uint32_t)b << 16);
}
__device__ __forceinline__ void split8(float4 v0, float4 v1, uint4& hh, uint4& ll) {
    uint16_t h[8], l[8];
    split2(v0.x, h[0], l[0]); split2(v0.y, h[1], l[1]);
    split2(v0.z, h[2], l[2]); split2(v0.w, h[3], l[3]);
    split2(v1.x, h[4], l[4]); split2(v1.y, h[5], l[5]);
    split2(v1.z, h[6], l[6]); split2(v1.w, h[7], l[7]);
    hh = make_uint4(pk(h[0],h[1]), pk(h[2],h[3]), pk(h[4],h[5]), pk(h[6],h[7]));
    ll = make_uint4(pk(l[0],l[1]), pk(l[2],l[3]), pk(l[4],l[5]), pk(l[6],l[7]));
}
// ldmatrix x4, non-transposed
__device__ __forceinline__ void ldsm4(uint32_t r[4], uint32_t addr) {
    asm volatile("ldmatrix.sync.aligned.m8n8.x4.shared.b16 {%0,%1,%2,%3}, [%4];"
        : "=r"(r[0]), "=r"(r[1]), "=r"(r[2]), "=r"(r[3]) : "r"(addr));
}
// D += A(16x16) * B(16x8), bf16 in, fp32 acc
__device__ __forceinline__ void mma_bf16(float d[4], const uint32_t a[4],
                                         uint32_t b0, uint32_t b1) {
    asm volatile(
        "mma.sync.aligned.m16n8k16.row.col.f32.bf16.bf16.f32 "
        "{%0,%1,%2,%3}, {%4,%5,%6,%7}, {%8,%9}, {%0,%1,%2,%3};"
        : "+f"(d[0]), "+f"(d[1]), "+f"(d[2]), "+f"(d[3])
        : "r"(a[0]), "r"(a[1]), "r"(a[2]), "r"(a[3]), "r"(b0), "r"(b1));
}

// ---------------------------------------------------------------------------
// prep: split embed (fp32) into bf16 hi/lo. 4 independent chunks/thread (MLP=4).
// total elems = NB*EMB_STRIDE = 1310720; 320 blocks x 256 thr x 4 chunks x 4 f
// ---------------------------------------------------------------------------
#define PREP_T (320 * 256)
__global__ __launch_bounds__(256) void prep_kernel(const float* __restrict__ embed)
{
    const size_t t = (size_t)blockIdx.x * 256 + threadIdx.x;
#pragma unroll
    for (int q = 0; q < 4; q++) {
        const size_t i = (t + (size_t)q * PREP_T) * 4;
        float4 v = *(const float4*)(embed + i);
        uint16_t h0, l0, h1, l1, h2, l2, h3, l3;
        split2(v.x, h0, l0); split2(v.y, h1, l1);
        split2(v.z, h2, l2); split2(v.w, h3, l3);
        *(uint2*)(g_w_hi + i) = make_uint2(pk(h0, h1), pk(h2, h3));
        *(uint2*)(g_w_lo + i) = make_uint2(pk(l0, l1), pk(l2, l3));
    }
}

// ---------------------------------------------------------------------------
// down: h_part[ks] = x[:,ksK:+K] @ Wdown[:,ksK:+K]^T, bf16x3 mma.sync.
// CTA: 64 rows x 64 cols, split-K=2 (10 K-chunks of 64). 8 warps, tile 32x16.
// ---------------------------------------------------------------------------
#define DST 72              // smem row stride in bf16 elems (conflict-free)
__global__ __launch_bounds__(256) void down_kernel(const float* __restrict__ x)
{
    __shared__ __align__(16) uint16_t sm[4 * 64 * DST];
    uint16_t* AH = sm;
    uint16_t* AL = sm + 64 * DST;
    uint16_t* BH = sm + 2 * 64 * DST;
    uint16_t* BL = sm + 3 * 64 * DST;

    const int tid = threadIdx.x, lane = tid & 31, wid = tid >> 5;
    const int ks = blockIdx.x, mt = blockIdx.y, b = blockIdx.z;
    const int kbeg = ks * KHALF;

    const float* A = x + ((size_t)b * SEQ + (size_t)mt * 64) * DIN;
    const __nv_bfloat16* WH = g_w_hi + (size_t)b * EMB_STRIDE;
    const __nv_bfloat16* WL = g_w_lo + (size_t)b * EMB_STRIDE;
    float* C = g_hpart + (size_t)ks * H_ELEMS + ((size_t)b * SEQ + (size_t)mt * 64) * RK;

    const int lrow = tid >> 2, lcs = (tid & 3) * 16;   // loader: row, 16-col seg
    const int wm = (wid & 1) * 32, wn = (wid >> 1) * 16; // warp tiling 2(M) x 4(N)

    const uint32_t ahb = s2u(AH), alb = s2u(AL), bhb = s2u(BH), blb = s2u(BL);
    const int aoff = (lane & 15) * DST + (lane >> 4) * 8;
    const int boff = (((lane >> 3) & 1) * 8 + (lane & 7)) * DST + (lane >> 4) * 8;

    float acc[2][2][4];
#pragma unroll
    for (int i = 0; i < 2; i++)
#pragma unroll
        for (int j = 0; j < 2; j++)
#pragma unroll
            for (int q = 0; q < 4; q++) acc[i][j][q] = 0.f;

    // prefetch chunk 0
    float4 xv0, xv1, xv2, xv3;
    uint4 whv0, whv1, wlv0, wlv1;
    {
        const float* ap = A + (size_t)lrow * DIN + kbeg + lcs;
        xv0 = *(const float4*)ap;       xv1 = *(const float4*)(ap + 4);
        xv2 = *(const float4*)(ap + 8); xv3 = *(const float4*)(ap + 12);
        const __nv_bfloat16* wp = WH + (size_t)lrow * DIN + kbeg + lcs;
        whv0 = *(const uint4*)wp; whv1 = *(const uint4*)(wp + 8);
        wp = WL + (size_t)lrow * DIN + kbeg + lcs;
        wlv0 = *(const uint4*)wp; wlv1 = *(const uint4*)(wp + 8);
    }

    for (int ch = 0; ch < KHALF / 64; ch++) {
        if (ch) __syncthreads();
        uint4 hh0, ll0, hh1, ll1;
        split8(xv0, xv1, hh0, ll0);
        split8(xv2, xv3, hh1, ll1);
        {
            uint16_t* p = AH + lrow * DST + lcs;
            *(uint4*)p = hh0; *(uint4*)(p + 8) = hh1;
            p = AL + lrow * DST + lcs;
            *(uint4*)p = ll0; *(uint4*)(p + 8) = ll1;
            p = BH + lrow * DST + lcs;
            *(uint4*)p = whv0; *(uint4*)(p + 8) = whv1;
            p = BL + lrow * DST + lcs;
            *(uint4*)p = wlv0; *(uint4*)(p + 8) = wlv1;
        }
        __syncthreads();

        if (ch + 1 < KHALF / 64) {            // prefetch next chunk over MMAs
            const int kc = kbeg + (ch + 1) * 64;
            const float* ap = A + (size_t)lrow * DIN + kc + lcs;
            xv0 = *(const float4*)ap;       xv1 = *(const float4*)(ap + 4);
            xv2 = *(const float4*)(ap + 8); xv3 = *(const float4*)(ap + 12);
            const __nv_bfloat16* wp = WH + (size_t)lrow * DIN + kc + lcs;
            whv0 = *(const uint4*)wp; whv1 = *(const uint4*)(wp + 8);
            wp = WL + (size_t)lrow * DIN + kc + lcs;
            wlv0 = *(const uint4*)wp; wlv1 = *(const uint4*)(wp + 8);
        }

#pragma unroll
        for (int ks2 = 0; ks2 < 4; ks2++) {
            const int kb = ks2 * 16;
            uint32_t ah0[4], ah1[4], al0[4], al1[4], bh[4], bl[4];
            ldsm4(ah0, ahb + (uint32_t)(wm * DST + kb + aoff) * 2);
            ldsm4(ah1, ahb + (uint32_t)((wm + 16) * DST + kb + aoff) * 2);
            ldsm4(al0, alb + (uint32_t)(wm * DST + kb + aoff) * 2);
            ldsm4(al1, alb + (uint32_t)((wm + 16) * DST + kb + aoff) * 2);
            ldsm4(bh,  bhb + (uint32_t)(wn * DST + kb + boff) * 2);
            ldsm4(bl,  blb + (uint32_t)(wn * DST + kb + boff) * 2);
            mma_bf16(acc[0][0], ah0, bh[0], bh[2]);
            mma_bf16(acc[0][0], ah0, bl[0], bl[2]);
            mma_bf16(acc[0][0], al0, bh[0], bh[2]);
            mma_bf16(acc[0][1], ah0, bh[1], bh[3]);
            mma_bf16(acc[0][1], ah0, bl[1], bl[3]);
            mma_bf16(acc[0][1], al0, bh[1], bh[3]);
            mma_bf16(acc[1][0], ah1, bh[0], bh[2]);
            mma_bf16(acc[1][0], ah1, bl[0], bl[2]);
            mma_bf16(acc[1][0], al1, bh[0], bh[2]);
            mma_bf16(acc[1][1], ah1, bh[1], bh[3]);
            mma_bf16(acc[1][1], ah1, bl[1], bl[3]);
            mma_bf16(acc[1][1], al1, bh[1], bh[3]);
        }
    }

    // epilogue: write fp32 partial h
    const int er = lane >> 2, ec = (lane & 3) * 2;
#pragma unroll
    for (int mf = 0; mf < 2; mf++)
#pragma unroll
        for (int nf = 0; nf < 2; nf++) {
            float* c0 = C + (size_t)(wm + mf * 16 + er) * RK + wn + nf * 8 + ec;
            *(float2*)c0            = make_float2(acc[mf][nf][0], acc[mf][nf][1]);
            *(float2*)(c0 + 8 * RK) = make_float2(acc[mf][nf][2], acc[mf][nf][3]);
        }
}

// ---------------------------------------------------------------------------
// reduce: h = part0 + part1, emitted once as bf16 hi/lo.
// ---------------------------------------------------------------------------
__global__ __launch_bounds__(256) void reduce_kernel()
{
    const size_t i = ((size_t)blockIdx.x * 256 + threadIdx.x) * 4;
    float4 a = *(const float4*)(g_hpart + i);
    float4 c = *(const float4*)(g_hpart + (size_t)H_ELEMS + i);
    a.x += c.x; a.y += c.y; a.z += c.z; a.w += c.w;
    uint16_t h0, l0, h1, l1, h2, l2, h3, l3;
    split2(a.x, h0, l0); split2(a.y, h1, l1);
    split2(a.z, h2, l2); split2(a.w, h3, l3);
    *(uint2*)(g_h_hi + i) = make_uint2(pk(h0, h1), pk(h2, h3));
    *(uint2*)(g_h_lo + i) = make_uint2(pk(l0, l1), pk(l2, l3));
}

// ---------------------------------------------------------------------------
// up: out = h @ Wup^T (per batch M=1024, N=1280, K=64), bf16x3 mma.sync.
// CTA: 128x128, single K-chunk, pure bf16 loads (no split work here).
// 8 warps, warp tile 32x64.
// ---------------------------------------------------------------------------
#define UP_SMEM_ELEMS (4 * 128 * DST)
__global__ __launch_bounds__(256) void up_kernel(float* __restrict__ out)
{
    extern __shared__ __align__(16) uint16_t usm[];
    uint16_t* AH = usm;
    uint16_t* AL = usm + 128 * DST;
    uint16_t* BH = usm + 2 * 128 * DST;
    uint16_t* BL = usm + 3 * 128 * DST;

    const int tid = threadIdx.x, lane = tid & 31, wid = tid >> 5;
    const int nt = blockIdx.x, mt = blockIdx.y, b = blockIdx.z;

    const __nv_bfloat16* hH = g_h_hi + ((size_t)b * SEQ + (size_t)mt * 128) * RK;
    const __nv_bfloat16* hL = g_h_lo + ((size_t)b * SEQ + (size_t)mt * 128) * RK;
    const __nv_bfloat16* WH = g_w_hi + (size_t)b * EMB_STRIDE + DOWN_SZ + (size_t)nt * 128 * RK;
    const __nv_bfloat16* WL = g_w_lo + (size_t)b * EMB_STRIDE + DOWN_SZ + (size_t)nt * 128 * RK;
    float* O = out + ((size_t)b * SEQ + (size_t)mt * 128) * DOUT + (size_t)nt * 128;

    // loaders: thread -> (row 0..127, 32-col segment); all pure bf16 copies
    const int lrow = tid >> 1, lcs = (tid & 1) * 32;
    {
        const __nv_bfloat16* ah = hH + (size_t)lrow * RK + lcs;
        const __nv_bfloat16* al = hL + (size_t)lrow * RK + lcs;
        const __nv_bfloat16* wh = WH + (size_t)lrow * RK + lcs;
        const __nv_bfloat16* wl = WL + (size_t)lrow * RK + lcs;
#pragma unroll
        for (int j = 0; j < 4; j++) {
            *(uint4*)(AH + lrow * DST + lcs + j * 8) = *(const uint4*)(ah + j * 8);
            *(uint4*)(AL + lrow * DST + lcs + j * 8) = *(const uint4*)(al + j * 8);
            *(uint4*)(BH + lrow * DST + lcs + j * 8) = *(const uint4*)(wh + j * 8);
            *(uint4*)(BL + lrow * DST + lcs + j * 8) = *(const uint4*)(wl + j * 8);
        }
    }
    __syncthreads();

    // warp tiling: 4 (M) x 2 (N); warp tile 32 x 64
    const int wm = (wid & 3) * 32, wn = (wid >> 2) * 64;
    const uint32_t ahb = s2u(AH), alb = s2u(AL), bhb = s2u(BH), blb = s2u(BL);
    const int aoff = (lane & 15) * DST + (lane >> 4) * 8;
    const int boff = (((lane >> 3) & 1) * 8 + (lane & 7)) * DST + (lane >> 4) * 8;

    float acc[2][8][4];
#pragma unroll
    for (int i = 0; i < 2; i++)
#pragma unroll
        for (int j = 0; j < 8; j++)
#pragma unroll
            for (int q = 0; q < 4; q++) acc[i][j][q] = 0.f;

#pragma unroll
    for (int ks = 0; ks < 4; ks++) {
        const int kb = ks * 16;
        uint32_t ah[2][4], al[2][4];
        ldsm4(ah[0], ahb + (uint32_t)(wm * DST + kb + aoff) * 2);
        ldsm4(ah[1], ahb + (uint32_t)((wm + 16) * DST + kb + aoff) * 2);
        ldsm4(al[0], alb + (uint32_t)(wm * DST + kb + aoff) * 2);
        ldsm4(al[1], alb + (uint32_t)((wm + 16) * DST + kb + aoff) * 2);
        uint32_t bh[4][4], bl[4][4];   // pair p covers nfrags 2p, 2p+1
#pragma unroll
        for (int p = 0; p < 4; p++) {
            ldsm4(bh[p], bhb + (uint32_t)((wn + p * 16) * DST + kb + boff) * 2);
            ldsm4(bl[p], blb + (uint32_t)((wn + p * 16) * DST + kb + boff) * 2);
        }
#pragma unroll
        for (int mf = 0; mf < 2; mf++)
#pragma unroll
            for (int p = 0; p < 4; p++) {
                mma_bf16(acc[mf][2*p],   ah[mf], bh[p][0], bh[p][2]);
                mma_bf16(acc[mf][2*p],   ah[mf], bl[p][0], bl[p][2]);
                mma_bf16(acc[mf][2*p],   al[mf], bh[p][0], bh[p][2]);
                mma_bf16(acc[mf][2*p+1], ah[mf], bh[p][1], bh[p][3]);
                mma_bf16(acc[mf][2*p+1], ah[mf], bl[p][1], bl[p][3]);
                mma_bf16(acc[mf][2*p+1], al[mf], bh[p][1], bh[p][3]);
            }
    }

    // epilogue: direct fp32 stores
    const int er = lane >> 2, ec = (lane & 3) * 2;
#pragma unroll
    for (int mf = 0; mf < 2; mf++)
#pragma unroll
        for (int nf = 0; nf < 8; nf++) {
            float* c0 = O + (size_t)(wm + mf * 16 + er) * DOUT + wn + nf * 8 + ec;
            *(float2*)c0              = make_float2(acc[mf][nf][0], acc[mf][nf][1]);
            *(float2*)(c0 + 8 * DOUT) = make_float2(acc[mf][nf][2], acc[mf][nf][3]);
        }
}

// ---------------------------------------------------------------------------
extern "C" void kernel_launch(void* const* d_in, const int* in_sizes, int n_in,
                              void* d_out, int out_size)
{
    const float* x     = (const float*)d_in[0];   // [B, S, D_IN] fp32
    const float* embed = (const float*)d_in[1];   // [B, DOWN+UP] fp32
    float*       out   = (float*)d_out;           // [B, S, D_OUT] fp32
    (void)in_sizes; (void)n_in; (void)out_size;

    cudaFuncSetAttribute(up_kernel, cudaFuncAttributeMaxDynamicSharedMemorySize,
                         UP_SMEM_ELEMS * 2);

    // 1) split embed into bf16 hi/lo (320 blocks, 4 chunks/thread)
    prep_kernel<<<320, 256>>>(embed);
    // 2) down GEMM split-K=2: grid 2 x 16 x 8 = 256 CTAs
    down_kernel<<<dim3(KSPLIT, SEQ / 64, NB), 256>>>(x);
    // 3) reduce partials -> bf16 hi/lo h (512 blocks)
    reduce_kernel<<<H_ELEMS / 4 / 256, 256>>>();
    // 4) up GEMM: grid 10 x 8 x 8 = 640 CTAs
    up_kernel<<<dim3(DOUT / 128, SEQ / 128, NB), 256, UP_SMEM_ELEMS * 2>>>(out);
}